// round 4
// baseline (speedup 1.0000x reference)
#include <cuda_runtime.h>
#include <math.h>

#define Bn 256
#define Fn 200
#define E1n 64
#define E2n 128
#define Hn 4
#define ROWS (Bn*Fn)              // 51200
#define ALPHAc 0.2f
#define NEGc -9000000000000000.0f

#define TROWS 64                  // attention row tile
#define AP2 68                    // attnT pad
#define CH 40                     // hs stream chunk rows (5 chunks of 40 = 200)

typedef unsigned long long ull;

__device__ float g_h[(size_t)Hn*ROWS*E2n];   // ~104.9 MB
__device__ float g_si[Hn*ROWS];
__device__ float g_sj[Hn*ROWS];

// ---- packed f32x2 helpers ----
__device__ __forceinline__ ull dup2(float v) {
    ull r; asm("mov.b64 %0, {%1, %1};" : "=l"(r) : "f"(v)); return r;
}
__device__ __forceinline__ void fma2(ull &d, ull a, ull b) {
    asm("fma.rn.f32x2 %0, %1, %2, %0;" : "+l"(d) : "l"(a), "l"(b));
}
__device__ __forceinline__ float2 unpk(ull v) {
    float2 r; asm("mov.b64 {%0, %1}, %2;" : "=f"(r.x), "=f"(r.y) : "l"(v)); return r;
}
__device__ __forceinline__ ull d2l(double d) { return __double_as_longlong(d); }

// ---- cp.async helpers ----
__device__ __forceinline__ void cp16(float* dst_smem, const float* src) {
    unsigned d = (unsigned)__cvta_generic_to_shared(dst_smem);
    asm volatile("cp.async.cg.shared.global [%0], [%1], 16;" :: "r"(d), "l"(src));
}
__device__ __forceinline__ void cp_commit() { asm volatile("cp.async.commit_group;"); }
__device__ __forceinline__ void cp_waitall() { asm volatile("cp.async.wait_group 0;" ::: "memory"); }

// ---------------------------------------------------------------------------
// Kernel 1: h[h,row,e] = sum_k x[row,k] * W[h,k,e], plus si/sj epilogue.
// ---------------------------------------------------------------------------
__global__ __launch_bounds__(256) void k_proj(const float* __restrict__ x,
                                              const float* __restrict__ W,
                                              const float* __restrict__ a) {
    extern __shared__ float sm[];
    float* xs = sm;               // [128][65]
    float* ws = sm + 128*65;      // [64][128]

    int tid  = threadIdx.x;
    int row0 = blockIdx.x * 128;

    const float4* xg = (const float4*)(x + (size_t)row0 * E1n);
    #pragma unroll
    for (int i = 0; i < 8; ++i) {
        int idx = tid + i * 256;
        float4 v = xg[idx];
        int r = idx >> 4, c = (idx & 15) << 2;
        float* p = &xs[r*65 + c];
        p[0] = v.x; p[1] = v.y; p[2] = v.z; p[3] = v.w;
    }

    int tr = tid >> 4;
    int tc = tid & 15;

    for (int h = 0; h < Hn; ++h) {
        __syncthreads();
        const float4* wg = (const float4*)(W + (size_t)h * E1n * E2n);
        float4* ws4 = (float4*)ws;
        #pragma unroll
        for (int i = 0; i < 8; ++i) ws4[tid + i*256] = wg[tid + i*256];
        __syncthreads();

        ull acc[32];
        #pragma unroll
        for (int i = 0; i < 32; ++i) acc[i] = 0ull;

        #pragma unroll 2
        for (int k = 0; k < E1n; ++k) {
            ull xd[8];
            #pragma unroll
            for (int r = 0; r < 8; ++r) xd[r] = dup2(xs[(tr*8 + r)*65 + k]);
            double2 w0 = *(const double2*)&ws[k*E2n + tc*8];
            double2 w1 = *(const double2*)&ws[k*E2n + tc*8 + 4];
            ull wv0 = d2l(w0.x), wv1 = d2l(w0.y), wv2 = d2l(w1.x), wv3 = d2l(w1.y);
            #pragma unroll
            for (int r = 0; r < 8; ++r) {
                fma2(acc[r*4+0], xd[r], wv0);
                fma2(acc[r*4+1], xd[r], wv1);
                fma2(acc[r*4+2], xd[r], wv2);
                fma2(acc[r*4+3], xd[r], wv3);
            }
        }

        const float* ap = a + (size_t)h * 2 * E2n;
        float4 ai0 = *(const float4*)&ap[tc*8];
        float4 ai1 = *(const float4*)&ap[tc*8 + 4];
        float4 aj0 = *(const float4*)&ap[E2n + tc*8];
        float4 aj1 = *(const float4*)&ap[E2n + tc*8 + 4];

        float* dst = g_h + ((size_t)h*ROWS + row0) * E2n;
        #pragma unroll
        for (int r = 0; r < 8; ++r) {
            float2 v0 = unpk(acc[r*4+0]);
            float2 v1 = unpk(acc[r*4+1]);
            float2 v2 = unpk(acc[r*4+2]);
            float2 v3 = unpk(acc[r*4+3]);
            size_t off = (size_t)(tr*8 + r)*E2n + tc*8;
            *(float4*)&dst[off]     = make_float4(v0.x, v0.y, v1.x, v1.y);
            *(float4*)&dst[off + 4] = make_float4(v2.x, v2.y, v3.x, v3.y);

            float pi = v0.x*ai0.x + v0.y*ai0.y + v1.x*ai0.z + v1.y*ai0.w
                     + v2.x*ai1.x + v2.y*ai1.y + v3.x*ai1.z + v3.y*ai1.w;
            float pj = v0.x*aj0.x + v0.y*aj0.y + v1.x*aj0.z + v1.y*aj0.w
                     + v2.x*aj1.x + v2.y*aj1.y + v3.x*aj1.z + v3.y*aj1.w;
            #pragma unroll
            for (int o = 8; o > 0; o >>= 1) {
                pi += __shfl_xor_sync(0xffffffffu, pi, o);
                pj += __shfl_xor_sync(0xffffffffu, pj, o);
            }
            if (tc == 0) {
                size_t gi = (size_t)h*ROWS + row0 + tr*8 + r;
                g_si[gi] = pi;
                g_sj[gi] = pj;
            }
        }
    }
}

// ---------------------------------------------------------------------------
// Kernel 2: fused masked-softmax attention + attn @ h.  CTA per (h, b).
// 64-row tiles; hs streamed via cp.async double buffer; 2 CTAs/SM.
// ---------------------------------------------------------------------------
__global__ __launch_bounds__(256) void k_attn(const float* __restrict__ adj,
                                              float* __restrict__ out) {
    extern __shared__ float smem[];
    float* attnT  = smem;                   // [200][AP2]
    float* hsbuf  = attnT + Fn*AP2;         // [2][CH][128]
    float* sjs    = hsbuf + 2*CH*E2n;       // 200
    float* sis    = sjs + Fn;               // 200
    float* rscale = sis + Fn;               // 64

    int h = blockIdx.x, b = blockIdx.y;
    int tid = threadIdx.x;
    size_t base = (size_t)h*ROWS + (size_t)b*Fn;
    const float* hsrc = g_h + base * E2n;   // 200x128 h tile in global

    for (int i = tid; i < Fn; i += 256) { sjs[i] = g_sj[base + i]; sis[i] = g_si[base + i]; }
    __syncthreads();    // sis/sjs visible to all threads before score phase

    int warp = tid >> 5, lane = tid & 31;
    int tr = tid >> 4;            // 0..15 -> rows tr*4 .. tr*4+3
    int tc = tid & 15;            // cols tc*8 .. tc*8+7

    for (int t0 = 0; t0 < Fn; t0 += TROWS) {
        int valid = Fn - t0; if (valid > TROWS) valid = TROWS;

        // prefetch hs chunk 0 into buf 0 (overlaps score phase)
        #pragma unroll
        for (int j = 0; j < 5; ++j) {
            int idx = (tid + j*256) * 4;            // float offset, 5120 floats/chunk
            cp16(&hsbuf[idx], &hsrc[idx]);
        }
        cp_commit();

        // ---- score phase: warp w handles rows rt = w, w+8, ..., w+56 ----
        #pragma unroll 1
        for (int rr = 0; rr < 8; ++rr) {
            int rt = rr*8 + warp;
            if (rt < valid) {
                int f = t0 + rt;
                float sif = sis[f];
                const float* adjrow = adj + (size_t)f * Fn;
                float s[7];
                #pragma unroll
                for (int j = 0; j < 7; ++j) {
                    int y = j*32 + lane;
                    if (y < Fn) {
                        float z = sif + sjs[y];
                        float e = (z > 0.f) ? z : ALPHAc * z;
                        float m = adjrow[y];
                        float mk = (m > 0.f) ? m : NEGc;
                        s[j] = e * mk;
                    } else s[j] = -INFINITY;
                }
                float mx = s[0];
                #pragma unroll
                for (int j = 1; j < 7; ++j) mx = fmaxf(mx, s[j]);
                #pragma unroll
                for (int o = 16; o > 0; o >>= 1) mx = fmaxf(mx, __shfl_xor_sync(0xffffffffu, mx, o));
                float p[7], sum = 0.f;
                #pragma unroll
                for (int j = 0; j < 7; ++j) { p[j] = __expf(s[j] - mx); sum += p[j]; }
                #pragma unroll
                for (int o = 16; o > 0; o >>= 1) sum += __shfl_xor_sync(0xffffffffu, sum, o);
                #pragma unroll
                for (int j = 0; j < 7; ++j) {
                    int y = j*32 + lane;
                    if (y < Fn) attnT[y*AP2 + rt] = p[j];
                }
                if (lane == 0) rscale[rt] = 1.f / sum;
            }
        }
        cp_waitall();
        __syncthreads();    // attnT + rscale + chunk0 visible

        // ---- GEMM: out_tile[64x128] = attn(64x200) @ h(200x128), streamed ----
        ull acc[16];
        #pragma unroll
        for (int i = 0; i < 16; ++i) acc[i] = 0ull;

        #pragma unroll 1
        for (int c = 0; c < 5; ++c) {
            if (c < 4) {
                const float* src = hsrc + (c+1)*CH*E2n;
                float* dst = hsbuf + ((c+1)&1)*CH*E2n;
                #pragma unroll
                for (int j = 0; j < 5; ++j) {
                    int idx = (tid + j*256) * 4;
                    cp16(&dst[idx], &src[idx]);
                }
                cp_commit();
            }
            const float* hb = hsbuf + (c&1)*CH*E2n;
            int ybase = c*CH;
            #pragma unroll 2
            for (int yy = 0; yy < CH; ++yy) {
                float4 av = *(const float4*)&attnT[(ybase+yy)*AP2 + tr*4];
                double2 h0 = *(const double2*)&hb[yy*E2n + tc*8];
                double2 h1 = *(const double2*)&hb[yy*E2n + tc*8 + 4];
                ull hv0 = d2l(h0.x), hv1 = d2l(h0.y), hv2 = d2l(h1.x), hv3 = d2l(h1.y);
                ull a0 = dup2(av.x), a1 = dup2(av.y), a2 = dup2(av.z), a3 = dup2(av.w);
                fma2(acc[0],  a0, hv0); fma2(acc[1],  a0, hv1); fma2(acc[2],  a0, hv2); fma2(acc[3],  a0, hv3);
                fma2(acc[4],  a1, hv0); fma2(acc[5],  a1, hv1); fma2(acc[6],  a1, hv2); fma2(acc[7],  a1, hv3);
                fma2(acc[8],  a2, hv0); fma2(acc[9],  a2, hv1); fma2(acc[10], a2, hv2); fma2(acc[11], a2, hv3);
                fma2(acc[12], a3, hv0); fma2(acc[13], a3, hv1); fma2(acc[14], a3, hv2); fma2(acc[15], a3, hv3);
            }
            if (c < 4) { cp_waitall(); __syncthreads(); }
        }

        // ---- epilogue ----
        #pragma unroll
        for (int r = 0; r < 4; ++r) {
            int rt = tr*4 + r;
            if (rt < valid) {
                int f = t0 + rt;
                float sc = rscale[rt];
                float2 v0 = unpk(acc[r*4+0]);
                float2 v1 = unpk(acc[r*4+1]);
                float2 v2 = unpk(acc[r*4+2]);
                float2 v3 = unpk(acc[r*4+3]);
                size_t o = ((size_t)b*Fn + f) * (Hn*E2n) + (size_t)h*E2n + tc*8;
                *(float4*)&out[o]     = make_float4(v0.x*sc, v0.y*sc, v1.x*sc, v1.y*sc);
                *(float4*)&out[o + 4] = make_float4(v2.x*sc, v2.y*sc, v3.x*sc, v3.y*sc);
            }
        }
        __syncthreads();   // attnT/rscale/hsbuf reuse by next tile
    }
}

// ---------------------------------------------------------------------------

extern "C" void kernel_launch(void* const* d_in, const int* in_sizes, int n_in,
                              void* d_out, int out_size) {
    const float* x   = (const float*)d_in[0];
    const float* adj = (const float*)d_in[1];
    const float* W   = (const float*)d_in[2];
    const float* a   = (const float*)d_in[3];
    float* out = (float*)d_out;

    const int SMEM_A = (128*65 + 64*128) * 4;                        // 66,048 B
    const int SMEM_B = (Fn*AP2 + 2*CH*E2n + Fn + Fn + TROWS) * 4;    // 97,216 B
    cudaFuncSetAttribute(k_proj, cudaFuncAttributeMaxDynamicSharedMemorySize, SMEM_A);
    cudaFuncSetAttribute(k_attn, cudaFuncAttributeMaxDynamicSharedMemorySize, SMEM_B);

    k_proj<<<ROWS/128, 256, SMEM_A>>>(x, W, a);             // 400 CTAs
    k_attn<<<dim3(Hn, Bn), 256, SMEM_B>>>(adj, out);        // 1,024 CTAs
}

// round 5
// speedup vs baseline: 1.1013x; 1.1013x over previous
#include <cuda_runtime.h>
#include <math.h>

#define Bn 256
#define Fn 200
#define E1n 64
#define E2n 128
#define Hn 4
#define ROWS (Bn*Fn)              // 51200
#define ALPHAc 0.2f
#define NEGc -9000000000000000.0f

#define TROWS 128                 // attention row tile (tiles: 128 + 72)
#define AP 132                    // attnT pad

typedef unsigned long long ull;

__device__ float g_h[(size_t)Hn*ROWS*E2n];   // ~104.9 MB
__device__ float g_si[Hn*ROWS];
__device__ float g_sj[Hn*ROWS];

// ---- packed f32x2 helpers ----
__device__ __forceinline__ ull dup2(float v) {
    ull r; asm("mov.b64 %0, {%1, %1};" : "=l"(r) : "f"(v)); return r;
}
__device__ __forceinline__ void fma2(ull &d, ull a, ull b) {
    asm("fma.rn.f32x2 %0, %1, %2, %0;" : "+l"(d) : "l"(a), "l"(b));
}
__device__ __forceinline__ float2 unpk(ull v) {
    float2 r; asm("mov.b64 {%0, %1}, %2;" : "=f"(r.x), "=f"(r.y) : "l"(v)); return r;
}
__device__ __forceinline__ ull d2l(double d) { return __double_as_longlong(d); }

// ---------------------------------------------------------------------------
// Kernel 1: h[h,row,e] = sum_k x[row,k] * W[h,k,e], plus si/sj epilogue.
// (proven config from round 2)
// ---------------------------------------------------------------------------
__global__ __launch_bounds__(256) void k_proj(const float* __restrict__ x,
                                              const float* __restrict__ W,
                                              const float* __restrict__ a) {
    extern __shared__ float sm[];
    float* xs = sm;               // [128][65]
    float* ws = sm + 128*65;      // [64][128]

    int tid  = threadIdx.x;
    int row0 = blockIdx.x * 128;

    const float4* xg = (const float4*)(x + (size_t)row0 * E1n);
    #pragma unroll
    for (int i = 0; i < 8; ++i) {
        int idx = tid + i * 256;
        float4 v = xg[idx];
        int r = idx >> 4, c = (idx & 15) << 2;
        float* p = &xs[r*65 + c];
        p[0] = v.x; p[1] = v.y; p[2] = v.z; p[3] = v.w;
    }

    int tr = tid >> 4;
    int tc = tid & 15;

    for (int h = 0; h < Hn; ++h) {
        __syncthreads();
        const float4* wg = (const float4*)(W + (size_t)h * E1n * E2n);
        float4* ws4 = (float4*)ws;
        #pragma unroll
        for (int i = 0; i < 8; ++i) ws4[tid + i*256] = wg[tid + i*256];
        __syncthreads();

        ull acc[32];
        #pragma unroll
        for (int i = 0; i < 32; ++i) acc[i] = 0ull;

        #pragma unroll 2
        for (int k = 0; k < E1n; ++k) {
            ull xd[8];
            #pragma unroll
            for (int r = 0; r < 8; ++r) xd[r] = dup2(xs[(tr*8 + r)*65 + k]);
            double2 w0 = *(const double2*)&ws[k*E2n + tc*8];
            double2 w1 = *(const double2*)&ws[k*E2n + tc*8 + 4];
            ull wv0 = d2l(w0.x), wv1 = d2l(w0.y), wv2 = d2l(w1.x), wv3 = d2l(w1.y);
            #pragma unroll
            for (int r = 0; r < 8; ++r) {
                fma2(acc[r*4+0], xd[r], wv0);
                fma2(acc[r*4+1], xd[r], wv1);
                fma2(acc[r*4+2], xd[r], wv2);
                fma2(acc[r*4+3], xd[r], wv3);
            }
        }

        const float* ap = a + (size_t)h * 2 * E2n;
        float4 ai0 = *(const float4*)&ap[tc*8];
        float4 ai1 = *(const float4*)&ap[tc*8 + 4];
        float4 aj0 = *(const float4*)&ap[E2n + tc*8];
        float4 aj1 = *(const float4*)&ap[E2n + tc*8 + 4];

        float* dst = g_h + ((size_t)h*ROWS + row0) * E2n;
        #pragma unroll
        for (int r = 0; r < 8; ++r) {
            float2 v0 = unpk(acc[r*4+0]);
            float2 v1 = unpk(acc[r*4+1]);
            float2 v2 = unpk(acc[r*4+2]);
            float2 v3 = unpk(acc[r*4+3]);
            size_t off = (size_t)(tr*8 + r)*E2n + tc*8;
            *(float4*)&dst[off]     = make_float4(v0.x, v0.y, v1.x, v1.y);
            *(float4*)&dst[off + 4] = make_float4(v2.x, v2.y, v3.x, v3.y);

            float pi = v0.x*ai0.x + v0.y*ai0.y + v1.x*ai0.z + v1.y*ai0.w
                     + v2.x*ai1.x + v2.y*ai1.y + v3.x*ai1.z + v3.y*ai1.w;
            float pj = v0.x*aj0.x + v0.y*aj0.y + v1.x*aj0.z + v1.y*aj0.w
                     + v2.x*aj1.x + v2.y*aj1.y + v3.x*aj1.z + v3.y*aj1.w;
            #pragma unroll
            for (int o = 8; o > 0; o >>= 1) {
                pi += __shfl_xor_sync(0xffffffffu, pi, o);
                pj += __shfl_xor_sync(0xffffffffu, pj, o);
            }
            if (tc == 0) {
                size_t gi = (size_t)h*ROWS + row0 + tr*8 + r;
                g_si[gi] = pi;
                g_sj[gi] = pj;
            }
        }
    }
}

// ---------------------------------------------------------------------------
// Kernel 2: fused masked-softmax attention + attn @ h.  CTA per (h, b).
// 512 threads, resident h tile, 128-row tiles, 4x8 thread tile (f32x2),
// ragged-tile GEMM early-out.
// smem: hs 200x128 + attnT 200x132 + sjs/sis/rscale = 210,112 B (1 CTA/SM)
// ---------------------------------------------------------------------------
__global__ __launch_bounds__(512) void k_attn(const float* __restrict__ adj,
                                              float* __restrict__ out) {
    extern __shared__ float smem[];
    float* hs     = smem;                   // [200][128]
    float* attnT  = hs + Fn*E2n;            // [200][AP]
    float* sjs    = attnT + Fn*AP;          // 200
    float* sis    = sjs + Fn;               // 200
    float* rscale = sis + Fn;               // 128

    int h = blockIdx.x, b = blockIdx.y;
    int tid = threadIdx.x;
    size_t base = (size_t)h*ROWS + (size_t)b*Fn;

    // stage h tile (once) and si/sj
    const float4* hg = (const float4*)(g_h + base * E2n);
    float4* hs4 = (float4*)hs;
    for (int i = tid; i < Fn*E2n/4; i += 512) hs4[i] = hg[i];
    for (int i = tid; i < Fn; i += 512) { sjs[i] = g_sj[base + i]; sis[i] = g_si[base + i]; }
    __syncthreads();

    int warp = tid >> 5, lane = tid & 31;
    int tr = tid >> 4;            // 0..31 -> rows tr*4 .. tr*4+3
    int tc = tid & 15;            // cols tc*8 .. tc*8+7

    for (int t0 = 0; t0 < Fn; t0 += TROWS) {
        int valid = Fn - t0; if (valid > TROWS) valid = TROWS;

        // ---- score phase: 16 warps, rows rt = rr*16 + warp ----
        #pragma unroll 1
        for (int rr = 0; rr < 8; ++rr) {
            int rt = rr*16 + warp;
            if (rt < valid) {
                int f = t0 + rt;
                float sif = sis[f];
                const float* adjrow = adj + (size_t)f * Fn;
                float s[7];
                #pragma unroll
                for (int j = 0; j < 7; ++j) {
                    int y = j*32 + lane;
                    if (y < Fn) {
                        float z = sif + sjs[y];
                        float e = (z > 0.f) ? z : ALPHAc * z;
                        float m = adjrow[y];
                        float mk = (m > 0.f) ? m : NEGc;
                        s[j] = e * mk;
                    } else s[j] = -INFINITY;
                }
                float mx = s[0];
                #pragma unroll
                for (int j = 1; j < 7; ++j) mx = fmaxf(mx, s[j]);
                #pragma unroll
                for (int o = 16; o > 0; o >>= 1) mx = fmaxf(mx, __shfl_xor_sync(0xffffffffu, mx, o));
                float p[7], sum = 0.f;
                #pragma unroll
                for (int j = 0; j < 7; ++j) { p[j] = __expf(s[j] - mx); sum += p[j]; }
                #pragma unroll
                for (int o = 16; o > 0; o >>= 1) sum += __shfl_xor_sync(0xffffffffu, sum, o);
                #pragma unroll
                for (int j = 0; j < 7; ++j) {
                    int y = j*32 + lane;
                    if (y < Fn) attnT[y*AP + rt] = p[j];
                }
                if (lane == 0) rscale[rt] = 1.f / sum;
            }
        }
        __syncthreads();    // attnT + rscale visible

        // ---- GEMM: out_tile[valid x 128] = attn @ hs; skip invalid rows ----
        if (tr*4 < valid) {
            ull acc[16];
            #pragma unroll
            for (int i = 0; i < 16; ++i) acc[i] = 0ull;

            #pragma unroll 2
            for (int y = 0; y < Fn; ++y) {
                float4 av = *(const float4*)&attnT[y*AP + tr*4];
                double2 h0 = *(const double2*)&hs[y*E2n + tc*8];
                double2 h1 = *(const double2*)&hs[y*E2n + tc*8 + 4];
                ull hv0 = d2l(h0.x), hv1 = d2l(h0.y), hv2 = d2l(h1.x), hv3 = d2l(h1.y);
                ull a0 = dup2(av.x), a1 = dup2(av.y), a2 = dup2(av.z), a3 = dup2(av.w);
                fma2(acc[0],  a0, hv0); fma2(acc[1],  a0, hv1); fma2(acc[2],  a0, hv2); fma2(acc[3],  a0, hv3);
                fma2(acc[4],  a1, hv0); fma2(acc[5],  a1, hv1); fma2(acc[6],  a1, hv2); fma2(acc[7],  a1, hv3);
                fma2(acc[8],  a2, hv0); fma2(acc[9],  a2, hv1); fma2(acc[10], a2, hv2); fma2(acc[11], a2, hv3);
                fma2(acc[12], a3, hv0); fma2(acc[13], a3, hv1); fma2(acc[14], a3, hv2); fma2(acc[15], a3, hv3);
            }

            // epilogue
            #pragma unroll
            for (int r = 0; r < 4; ++r) {
                int rt = tr*4 + r;
                if (rt < valid) {
                    int f = t0 + rt;
                    float sc = rscale[rt];
                    float2 v0 = unpk(acc[r*4+0]);
                    float2 v1 = unpk(acc[r*4+1]);
                    float2 v2 = unpk(acc[r*4+2]);
                    float2 v3 = unpk(acc[r*4+3]);
                    size_t o = ((size_t)b*Fn + f) * (Hn*E2n) + (size_t)h*E2n + tc*8;
                    *(float4*)&out[o]     = make_float4(v0.x*sc, v0.y*sc, v1.x*sc, v1.y*sc);
                    *(float4*)&out[o + 4] = make_float4(v2.x*sc, v2.y*sc, v3.x*sc, v3.y*sc);
                }
            }
        }
        __syncthreads();   // attnT/rscale reuse by next tile
    }
}

// ---------------------------------------------------------------------------

extern "C" void kernel_launch(void* const* d_in, const int* in_sizes, int n_in,
                              void* d_out, int out_size) {
    const float* x   = (const float*)d_in[0];
    const float* adj = (const float*)d_in[1];
    const float* W   = (const float*)d_in[2];
    const float* a   = (const float*)d_in[3];
    float* out = (float*)d_out;

    const int SMEM_A = (128*65 + 64*128) * 4;                      // 66,048 B
    const int SMEM_B = (Fn*E2n + Fn*AP + Fn + Fn + TROWS) * 4;     // 210,112 B
    cudaFuncSetAttribute(k_proj, cudaFuncAttributeMaxDynamicSharedMemorySize, SMEM_A);
    cudaFuncSetAttribute(k_attn, cudaFuncAttributeMaxDynamicSharedMemorySize, SMEM_B);

    k_proj<<<ROWS/128, 256, SMEM_A>>>(x, W, a);             // 400 CTAs
    k_attn<<<dim3(Hn, Bn), 512, SMEM_B>>>(adj, out);        // 1,024 CTAs
}

// round 6
// speedup vs baseline: 1.2784x; 1.1608x over previous
#include <cuda_runtime.h>
#include <math.h>

#define Bn 256
#define Fn 200
#define E1n 64
#define E2n 128
#define Hn 4
#define ROWS (Bn*Fn)              // 51200
#define ALPHAc 0.2f
#define NEGc -9000000000000000.0f

#define TROWS 128                 // attention row tile (tiles: 128 + 72)
#define AP 132                    // attnT pad

typedef unsigned long long ull;

__device__ float g_h[(size_t)Hn*ROWS*E2n];   // ~104.9 MB
__device__ float g_si[Hn*ROWS];
__device__ float g_sj[Hn*ROWS];

// ---- packed f32x2 helpers ----
__device__ __forceinline__ ull dup2(float v) {
    ull r; asm("mov.b64 %0, {%1, %1};" : "=l"(r) : "f"(v)); return r;
}
__device__ __forceinline__ void fma2(ull &d, ull a, ull b) {
    asm("fma.rn.f32x2 %0, %1, %2, %0;" : "+l"(d) : "l"(a), "l"(b));
}
__device__ __forceinline__ float2 unpk(ull v) {
    float2 r; asm("mov.b64 {%0, %1}, %2;" : "=f"(r.x), "=f"(r.y) : "l"(v)); return r;
}
__device__ __forceinline__ ull d2l(double d) { return __double_as_longlong(d); }

// 8x8 f32x2 outer-product step: 8 dups + 32 fma2
#define GEMM_STEP(AV0, AV1, H0, H1)                                        \
    {                                                                      \
        ull hv0 = d2l(H0.x), hv1 = d2l(H0.y), hv2 = d2l(H1.x), hv3 = d2l(H1.y); \
        ull q0 = dup2(AV0.x), q1 = dup2(AV0.y), q2 = dup2(AV0.z), q3 = dup2(AV0.w); \
        ull q4 = dup2(AV1.x), q5 = dup2(AV1.y), q6 = dup2(AV1.z), q7 = dup2(AV1.w); \
        fma2(acc[0],  q0, hv0); fma2(acc[1],  q0, hv1); fma2(acc[2],  q0, hv2); fma2(acc[3],  q0, hv3); \
        fma2(acc[4],  q1, hv0); fma2(acc[5],  q1, hv1); fma2(acc[6],  q1, hv2); fma2(acc[7],  q1, hv3); \
        fma2(acc[8],  q2, hv0); fma2(acc[9],  q2, hv1); fma2(acc[10], q2, hv2); fma2(acc[11], q2, hv3); \
        fma2(acc[12], q3, hv0); fma2(acc[13], q3, hv1); fma2(acc[14], q3, hv2); fma2(acc[15], q3, hv3); \
        fma2(acc[16], q4, hv0); fma2(acc[17], q4, hv1); fma2(acc[18], q4, hv2); fma2(acc[19], q4, hv3); \
        fma2(acc[20], q5, hv0); fma2(acc[21], q5, hv1); fma2(acc[22], q5, hv2); fma2(acc[23], q5, hv3); \
        fma2(acc[24], q6, hv0); fma2(acc[25], q6, hv1); fma2(acc[26], q6, hv2); fma2(acc[27], q6, hv3); \
        fma2(acc[28], q7, hv0); fma2(acc[29], q7, hv1); fma2(acc[30], q7, hv2); fma2(acc[31], q7, hv3); \
    }

// ---------------------------------------------------------------------------
// Kernel 1: h[h,row,e] = sum_k x[row,k] * W[h,k,e], plus si/sj epilogue.
// ---------------------------------------------------------------------------
__global__ __launch_bounds__(256) void k_proj(const float* __restrict__ x,
                                              const float* __restrict__ W,
                                              const float* __restrict__ a) {
    extern __shared__ float sm[];
    float* xs = sm;               // [128][65]
    float* ws = sm + 128*65;      // [64][128]

    int tid  = threadIdx.x;
    int row0 = blockIdx.x * 128;

    const float4* xg = (const float4*)(x + (size_t)row0 * E1n);
    #pragma unroll
    for (int i = 0; i < 8; ++i) {
        int idx = tid + i * 256;
        float4 v = xg[idx];
        int r = idx >> 4, c = (idx & 15) << 2;
        float* p = &xs[r*65 + c];
        p[0] = v.x; p[1] = v.y; p[2] = v.z; p[3] = v.w;
    }

    int tr = tid >> 4;
    int tc = tid & 15;

    for (int h = 0; h < Hn; ++h) {
        __syncthreads();
        const float4* wg = (const float4*)(W + (size_t)h * E1n * E2n);
        float4* ws4 = (float4*)ws;
        #pragma unroll
        for (int i = 0; i < 8; ++i) ws4[tid + i*256] = wg[tid + i*256];
        __syncthreads();

        ull acc[32];
        #pragma unroll
        for (int i = 0; i < 32; ++i) acc[i] = 0ull;

        #pragma unroll 2
        for (int k = 0; k < E1n; ++k) {
            ull xd[8];
            #pragma unroll
            for (int r = 0; r < 8; ++r) xd[r] = dup2(xs[(tr*8 + r)*65 + k]);
            double2 w0 = *(const double2*)&ws[k*E2n + tc*8];
            double2 w1 = *(const double2*)&ws[k*E2n + tc*8 + 4];
            ull wv0 = d2l(w0.x), wv1 = d2l(w0.y), wv2 = d2l(w1.x), wv3 = d2l(w1.y);
            #pragma unroll
            for (int r = 0; r < 8; ++r) {
                fma2(acc[r*4+0], xd[r], wv0);
                fma2(acc[r*4+1], xd[r], wv1);
                fma2(acc[r*4+2], xd[r], wv2);
                fma2(acc[r*4+3], xd[r], wv3);
            }
        }

        const float* ap = a + (size_t)h * 2 * E2n;
        float4 ai0 = *(const float4*)&ap[tc*8];
        float4 ai1 = *(const float4*)&ap[tc*8 + 4];
        float4 aj0 = *(const float4*)&ap[E2n + tc*8];
        float4 aj1 = *(const float4*)&ap[E2n + tc*8 + 4];

        float* dst = g_h + ((size_t)h*ROWS + row0) * E2n;
        #pragma unroll
        for (int r = 0; r < 8; ++r) {
            float2 v0 = unpk(acc[r*4+0]);
            float2 v1 = unpk(acc[r*4+1]);
            float2 v2 = unpk(acc[r*4+2]);
            float2 v3 = unpk(acc[r*4+3]);
            size_t off = (size_t)(tr*8 + r)*E2n + tc*8;
            *(float4*)&dst[off]     = make_float4(v0.x, v0.y, v1.x, v1.y);
            *(float4*)&dst[off + 4] = make_float4(v2.x, v2.y, v3.x, v3.y);

            float pi = v0.x*ai0.x + v0.y*ai0.y + v1.x*ai0.z + v1.y*ai0.w
                     + v2.x*ai1.x + v2.y*ai1.y + v3.x*ai1.z + v3.y*ai1.w;
            float pj = v0.x*aj0.x + v0.y*aj0.y + v1.x*aj0.z + v1.y*aj0.w
                     + v2.x*aj1.x + v2.y*aj1.y + v3.x*aj1.z + v3.y*aj1.w;
            #pragma unroll
            for (int o = 8; o > 0; o >>= 1) {
                pi += __shfl_xor_sync(0xffffffffu, pi, o);
                pj += __shfl_xor_sync(0xffffffffu, pj, o);
            }
            if (tc == 0) {
                size_t gi = (size_t)h*ROWS + row0 + tr*8 + r;
                g_si[gi] = pi;
                g_sj[gi] = pj;
            }
        }
    }
}

// ---------------------------------------------------------------------------
// Kernel 2: fused masked-softmax attention + attn @ h.  CTA per (h, b).
// 256 threads, resident h tile, 128-row tiles, 8x8 f32x2 thread tile,
// 2-row-interleaved score phase, 2-deep software-pipelined GEMM.
// smem: hs 200x128 + attnT 200x132 + sjs/sis/rscale = 210,112 B (1 CTA/SM)
// ---------------------------------------------------------------------------
__global__ __launch_bounds__(256) void k_attn(const float* __restrict__ adj,
                                              float* __restrict__ out) {
    extern __shared__ float smem[];
    float* hs     = smem;                   // [200][128]
    float* attnT  = hs + Fn*E2n;            // [200][AP]
    float* sjs    = attnT + Fn*AP;          // 200
    float* sis    = sjs + Fn;               // 200
    float* rscale = sis + Fn;               // 128

    int h = blockIdx.x, b = blockIdx.y;
    int tid = threadIdx.x;
    size_t base = (size_t)h*ROWS + (size_t)b*Fn;

    const float4* hg = (const float4*)(g_h + base * E2n);
    float4* hs4 = (float4*)hs;
    for (int i = tid; i < Fn*E2n/4; i += 256) hs4[i] = hg[i];
    for (int i = tid; i < Fn; i += 256) { sjs[i] = g_sj[base + i]; sis[i] = g_si[base + i]; }
    __syncthreads();

    int warp = tid >> 5, lane = tid & 31;
    int tr = tid >> 4;            // 0..15 -> rows tr*8 .. tr*8+7
    int tc = tid & 15;            // cols tc*8 .. tc*8+7

    for (int t0 = 0; t0 < Fn; t0 += TROWS) {
        int valid = Fn - t0; if (valid > TROWS) valid = TROWS;

        // ---- score phase: each warp processes row-pairs (rt, rt+8) ----
        #pragma unroll 1
        for (int p = 0; p < 8; ++p) {
            int rt0 = p*16 + warp;
            int rt1 = rt0 + 8;
            bool v0 = rt0 < valid, v1 = rt1 < valid;   // warp-uniform
            if (!v0) break;

            int f0 = t0 + rt0, f1 = t0 + rt1;
            float si0 = sis[f0];
            float si1 = v1 ? sis[f1] : 0.f;
            const float* r0p = adj + (size_t)f0 * Fn;
            const float* r1p = adj + (size_t)f1 * Fn;

            float s0[7], s1[7];
            #pragma unroll
            for (int j = 0; j < 7; ++j) {
                int y = j*32 + lane;
                if (y < Fn) {
                    float sjv = sjs[y];
                    float m0 = r0p[y];
                    float z0 = si0 + sjv;
                    float e0 = (z0 > 0.f) ? z0 : ALPHAc * z0;
                    s0[j] = e0 * ((m0 > 0.f) ? m0 : NEGc);
                    if (v1) {
                        float m1 = r1p[y];
                        float z1 = si1 + sjv;
                        float e1 = (z1 > 0.f) ? z1 : ALPHAc * z1;
                        s1[j] = e1 * ((m1 > 0.f) ? m1 : NEGc);
                    } else s1[j] = -INFINITY;
                } else { s0[j] = -INFINITY; s1[j] = -INFINITY; }
            }

            float mx0 = s0[0], mx1 = s1[0];
            #pragma unroll
            for (int j = 1; j < 7; ++j) { mx0 = fmaxf(mx0, s0[j]); mx1 = fmaxf(mx1, s1[j]); }
            #pragma unroll
            for (int o = 16; o > 0; o >>= 1) {
                mx0 = fmaxf(mx0, __shfl_xor_sync(0xffffffffu, mx0, o));
                mx1 = fmaxf(mx1, __shfl_xor_sync(0xffffffffu, mx1, o));
            }
            float p0[7], p1[7], sum0 = 0.f, sum1 = 0.f;
            #pragma unroll
            for (int j = 0; j < 7; ++j) {
                p0[j] = __expf(s0[j] - mx0); sum0 += p0[j];
                p1[j] = __expf(s1[j] - mx1); sum1 += p1[j];
            }
            #pragma unroll
            for (int o = 16; o > 0; o >>= 1) {
                sum0 += __shfl_xor_sync(0xffffffffu, sum0, o);
                sum1 += __shfl_xor_sync(0xffffffffu, sum1, o);
            }
            #pragma unroll
            for (int j = 0; j < 7; ++j) {
                int y = j*32 + lane;
                if (y < Fn) {
                    attnT[y*AP + rt0] = p0[j];
                    if (v1) attnT[y*AP + rt1] = p1[j];
                }
            }
            if (lane == 0) {
                rscale[rt0] = 1.f / sum0;
                if (v1) rscale[rt1] = 1.f / sum1;
            }
        }
        __syncthreads();    // attnT + rscale visible

        // ---- GEMM: out_tile[valid x 128] = attn @ hs (2-deep pipeline) ----
        if (tr*8 < valid) {
            ull acc[32];
            #pragma unroll
            for (int i = 0; i < 32; ++i) acc[i] = 0ull;

            const float* aB = attnT + tr*8;
            const float* hB = hs + tc*8;

            float4 avA0 = *(const float4*)&aB[0*AP];
            float4 avA1 = *(const float4*)&aB[0*AP + 4];
            double2 hA0 = *(const double2*)&hB[0*E2n];
            double2 hA1 = *(const double2*)&hB[0*E2n + 4];
            float4 avB0 = *(const float4*)&aB[1*AP];
            float4 avB1 = *(const float4*)&aB[1*AP + 4];
            double2 hB0 = *(const double2*)&hB[1*E2n];
            double2 hB1 = *(const double2*)&hB[1*E2n + 4];

            #pragma unroll 1
            for (int y = 0; y < Fn - 2; y += 2) {
                GEMM_STEP(avA0, avA1, hA0, hA1);
                avA0 = *(const float4*)&aB[(y+2)*AP];
                avA1 = *(const float4*)&aB[(y+2)*AP + 4];
                hA0  = *(const double2*)&hB[(y+2)*E2n];
                hA1  = *(const double2*)&hB[(y+2)*E2n + 4];
                GEMM_STEP(avB0, avB1, hB0, hB1);
                avB0 = *(const float4*)&aB[(y+3)*AP];
                avB1 = *(const float4*)&aB[(y+3)*AP + 4];
                hB0  = *(const double2*)&hB[(y+3)*E2n];
                hB1  = *(const double2*)&hB[(y+3)*E2n + 4];
            }
            GEMM_STEP(avA0, avA1, hA0, hA1);
            GEMM_STEP(avB0, avB1, hB0, hB1);

            // epilogue
            #pragma unroll
            for (int r = 0; r < 8; ++r) {
                int rt = tr*8 + r;
                if (rt < valid) {
                    int f = t0 + rt;
                    float sc = rscale[rt];
                    float2 v0 = unpk(acc[r*4+0]);
                    float2 v1 = unpk(acc[r*4+1]);
                    float2 v2 = unpk(acc[r*4+2]);
                    float2 v3 = unpk(acc[r*4+3]);
                    size_t o = ((size_t)b*Fn + f) * (Hn*E2n) + (size_t)h*E2n + tc*8;
                    *(float4*)&out[o]     = make_float4(v0.x*sc, v0.y*sc, v1.x*sc, v1.y*sc);
                    *(float4*)&out[o + 4] = make_float4(v2.x*sc, v2.y*sc, v3.x*sc, v3.y*sc);
                }
            }
        }
        __syncthreads();   // attnT/rscale reuse by next tile
    }
}

// ---------------------------------------------------------------------------

extern "C" void kernel_launch(void* const* d_in, const int* in_sizes, int n_in,
                              void* d_out, int out_size) {
    const float* x   = (const float*)d_in[0];
    const float* adj = (const float*)d_in[1];
    const float* W   = (const float*)d_in[2];
    const float* a   = (const float*)d_in[3];
    float* out = (float*)d_out;

    const int SMEM_A = (128*65 + 64*128) * 4;                      // 66,048 B
    const int SMEM_B = (Fn*E2n + Fn*AP + Fn + Fn + TROWS) * 4;     // 210,112 B
    cudaFuncSetAttribute(k_proj, cudaFuncAttributeMaxDynamicSharedMemorySize, SMEM_A);
    cudaFuncSetAttribute(k_attn, cudaFuncAttributeMaxDynamicSharedMemorySize, SMEM_B);

    k_proj<<<ROWS/128, 256, SMEM_A>>>(x, W, a);             // 400 CTAs
    k_attn<<<dim3(Hn, Bn), 256, SMEM_B>>>(adj, out);        // 1,024 CTAs
}

// round 7
// speedup vs baseline: 1.2818x; 1.0027x over previous
#include <cuda_runtime.h>
#include <math.h>

#define Bn 256
#define Fn 200
#define E1n 64
#define E2n 128
#define Hn 4
#define ROWS (Bn*Fn)              // 51200
#define ALPHAc 0.2f
#define NEGc -9000000000000000.0f

#define TROWS 128                 // attention row tile (tiles: 128 + 72)
#define AP 132                    // attnT pad / reduction-buffer stride
#define KSPLIT 100                // y per warp-group

typedef unsigned long long ull;

__device__ float g_h[(size_t)Hn*ROWS*E2n];   // ~104.9 MB
__device__ float g_si[Hn*ROWS];
__device__ float g_sj[Hn*ROWS];

// ---- packed f32x2 helpers ----
__device__ __forceinline__ ull dup2(float v) {
    ull r; asm("mov.b64 %0, {%1, %1};" : "=l"(r) : "f"(v)); return r;
}
__device__ __forceinline__ void fma2(ull &d, ull a, ull b) {
    asm("fma.rn.f32x2 %0, %1, %2, %0;" : "+l"(d) : "l"(a), "l"(b));
}
__device__ __forceinline__ void add2(ull &d, ull a) {
    asm("add.rn.f32x2 %0, %0, %1;" : "+l"(d) : "l"(a));
}
__device__ __forceinline__ float2 unpk(ull v) {
    float2 r; asm("mov.b64 {%0, %1}, %2;" : "=f"(r.x), "=f"(r.y) : "l"(v)); return r;
}
__device__ __forceinline__ ull d2l(double d) { return __double_as_longlong(d); }

// 8x8 f32x2 outer-product step: 8 dups + 32 fma2
#define GEMM_STEP(AV0, AV1, H0, H1)                                        \
    {                                                                      \
        ull hv0 = d2l(H0.x), hv1 = d2l(H0.y), hv2 = d2l(H1.x), hv3 = d2l(H1.y); \
        ull q0 = dup2(AV0.x), q1 = dup2(AV0.y), q2 = dup2(AV0.z), q3 = dup2(AV0.w); \
        ull q4 = dup2(AV1.x), q5 = dup2(AV1.y), q6 = dup2(AV1.z), q7 = dup2(AV1.w); \
        fma2(acc[0],  q0, hv0); fma2(acc[1],  q0, hv1); fma2(acc[2],  q0, hv2); fma2(acc[3],  q0, hv3); \
        fma2(acc[4],  q1, hv0); fma2(acc[5],  q1, hv1); fma2(acc[6],  q1, hv2); fma2(acc[7],  q1, hv3); \
        fma2(acc[8],  q2, hv0); fma2(acc[9],  q2, hv1); fma2(acc[10], q2, hv2); fma2(acc[11], q2, hv3); \
        fma2(acc[12], q3, hv0); fma2(acc[13], q3, hv1); fma2(acc[14], q3, hv2); fma2(acc[15], q3, hv3); \
        fma2(acc[16], q4, hv0); fma2(acc[17], q4, hv1); fma2(acc[18], q4, hv2); fma2(acc[19], q4, hv3); \
        fma2(acc[20], q5, hv0); fma2(acc[21], q5, hv1); fma2(acc[22], q5, hv2); fma2(acc[23], q5, hv3); \
        fma2(acc[24], q6, hv0); fma2(acc[25], q6, hv1); fma2(acc[26], q6, hv2); fma2(acc[27], q6, hv3); \
        fma2(acc[28], q7, hv0); fma2(acc[29], q7, hv1); fma2(acc[30], q7, hv2); fma2(acc[31], q7, hv3); \
    }

// ---------------------------------------------------------------------------
// Kernel 1: h[h,row,e] = sum_k x[row,k] * W[h,k,e], plus si/sj epilogue.
// ---------------------------------------------------------------------------
__global__ __launch_bounds__(256) void k_proj(const float* __restrict__ x,
                                              const float* __restrict__ W,
                                              const float* __restrict__ a) {
    extern __shared__ float sm[];
    float* xs = sm;               // [128][65]
    float* ws = sm + 128*65;      // [64][128]

    int tid  = threadIdx.x;
    int row0 = blockIdx.x * 128;

    const float4* xg = (const float4*)(x + (size_t)row0 * E1n);
    #pragma unroll
    for (int i = 0; i < 8; ++i) {
        int idx = tid + i * 256;
        float4 v = xg[idx];
        int r = idx >> 4, c = (idx & 15) << 2;
        float* p = &xs[r*65 + c];
        p[0] = v.x; p[1] = v.y; p[2] = v.z; p[3] = v.w;
    }

    int tr = tid >> 4;
    int tc = tid & 15;

    for (int h = 0; h < Hn; ++h) {
        __syncthreads();
        const float4* wg = (const float4*)(W + (size_t)h * E1n * E2n);
        float4* ws4 = (float4*)ws;
        #pragma unroll
        for (int i = 0; i < 8; ++i) ws4[tid + i*256] = wg[tid + i*256];
        __syncthreads();

        ull acc[32];
        #pragma unroll
        for (int i = 0; i < 32; ++i) acc[i] = 0ull;

        #pragma unroll 2
        for (int k = 0; k < E1n; ++k) {
            ull xd[8];
            #pragma unroll
            for (int r = 0; r < 8; ++r) xd[r] = dup2(xs[(tr*8 + r)*65 + k]);
            double2 w0 = *(const double2*)&ws[k*E2n + tc*8];
            double2 w1 = *(const double2*)&ws[k*E2n + tc*8 + 4];
            ull wv0 = d2l(w0.x), wv1 = d2l(w0.y), wv2 = d2l(w1.x), wv3 = d2l(w1.y);
            #pragma unroll
            for (int r = 0; r < 8; ++r) {
                fma2(acc[r*4+0], xd[r], wv0);
                fma2(acc[r*4+1], xd[r], wv1);
                fma2(acc[r*4+2], xd[r], wv2);
                fma2(acc[r*4+3], xd[r], wv3);
            }
        }

        const float* ap = a + (size_t)h * 2 * E2n;
        float4 ai0 = *(const float4*)&ap[tc*8];
        float4 ai1 = *(const float4*)&ap[tc*8 + 4];
        float4 aj0 = *(const float4*)&ap[E2n + tc*8];
        float4 aj1 = *(const float4*)&ap[E2n + tc*8 + 4];

        float* dst = g_h + ((size_t)h*ROWS + row0) * E2n;
        #pragma unroll
        for (int r = 0; r < 8; ++r) {
            float2 v0 = unpk(acc[r*4+0]);
            float2 v1 = unpk(acc[r*4+1]);
            float2 v2 = unpk(acc[r*4+2]);
            float2 v3 = unpk(acc[r*4+3]);
            size_t off = (size_t)(tr*8 + r)*E2n + tc*8;
            *(float4*)&dst[off]     = make_float4(v0.x, v0.y, v1.x, v1.y);
            *(float4*)&dst[off + 4] = make_float4(v2.x, v2.y, v3.x, v3.y);

            float pi = v0.x*ai0.x + v0.y*ai0.y + v1.x*ai0.z + v1.y*ai0.w
                     + v2.x*ai1.x + v2.y*ai1.y + v3.x*ai1.z + v3.y*ai1.w;
            float pj = v0.x*aj0.x + v0.y*aj0.y + v1.x*aj0.z + v1.y*aj0.w
                     + v2.x*aj1.x + v2.y*aj1.y + v3.x*aj1.z + v3.y*aj1.w;
            #pragma unroll
            for (int o = 8; o > 0; o >>= 1) {
                pi += __shfl_xor_sync(0xffffffffu, pi, o);
                pj += __shfl_xor_sync(0xffffffffu, pj, o);
            }
            if (tc == 0) {
                size_t gi = (size_t)h*ROWS + row0 + tr*8 + r;
                g_si[gi] = pi;
                g_sj[gi] = pj;
            }
        }
    }
}

// ---------------------------------------------------------------------------
// Kernel 2: fused masked-softmax attention + attn @ h.  CTA per (h, b).
// 512 threads = 2 warp-groups split-K over y (A: y<100, B: y>=100).
// Each group: 8x8 f32x2 thread tile over 128x128. B's partials reduced
// through the (then-dead) attnT region. 4 warps/SMSP for latency hiding.
// ---------------------------------------------------------------------------
__global__ __launch_bounds__(512) void k_attn(const float* __restrict__ adj,
                                              float* __restrict__ out) {
    extern __shared__ float smem[];
    float* hs     = smem;                   // [200][128]
    float* attnT  = hs + Fn*E2n;            // [200][AP]  (also reduction buf)
    float* sjs    = attnT + Fn*AP;          // 200
    float* sis    = sjs + Fn;               // 200
    float* rscale = sis + Fn;               // 128

    int h = blockIdx.x, b = blockIdx.y;
    int tid = threadIdx.x;
    size_t base = (size_t)h*ROWS + (size_t)b*Fn;

    const float4* hg = (const float4*)(g_h + base * E2n);
    float4* hs4 = (float4*)hs;
    for (int i = tid; i < Fn*E2n/4; i += 512) hs4[i] = hg[i];
    for (int i = tid; i < Fn; i += 512) { sjs[i] = g_sj[base + i]; sis[i] = g_si[base + i]; }
    __syncthreads();

    int warp = tid >> 5, lane = tid & 31;
    int grp  = tid >> 8;          // 0: y in [0,100), 1: y in [100,200)
    int gt   = tid & 255;
    int tr   = gt >> 4;           // 0..15 -> rows tr*8 .. tr*8+7
    int tc   = gt & 15;           // cols tc*8 .. tc*8+7
    int y0   = grp * KSPLIT;

    for (int t0 = 0; t0 < Fn; t0 += TROWS) {
        int valid = Fn - t0; if (valid > TROWS) valid = TROWS;
        bool gemm_on = (tr*8 < valid);

        // ---- score phase: 16 warps, row-pairs (rt0, rt0+16) ----
        #pragma unroll 1
        for (int p = 0; p < 4; ++p) {
            int rt0 = p*32 + warp;
            int rt1 = rt0 + 16;
            bool v0 = rt0 < valid, v1 = rt1 < valid;   // warp-uniform
            if (!v0) continue;

            int f0 = t0 + rt0, f1 = t0 + rt1;
            float si0 = sis[f0];
            float si1 = v1 ? sis[f1] : 0.f;
            const float* r0p = adj + (size_t)f0 * Fn;
            const float* r1p = adj + (size_t)f1 * Fn;

            float s0[7], s1[7];
            #pragma unroll
            for (int j = 0; j < 7; ++j) {
                int y = j*32 + lane;
                if (y < Fn) {
                    float sjv = sjs[y];
                    float m0 = r0p[y];
                    float z0 = si0 + sjv;
                    float e0 = (z0 > 0.f) ? z0 : ALPHAc * z0;
                    s0[j] = e0 * ((m0 > 0.f) ? m0 : NEGc);
                    if (v1) {
                        float m1 = r1p[y];
                        float z1 = si1 + sjv;
                        float e1 = (z1 > 0.f) ? z1 : ALPHAc * z1;
                        s1[j] = e1 * ((m1 > 0.f) ? m1 : NEGc);
                    } else s1[j] = -INFINITY;
                } else { s0[j] = -INFINITY; s1[j] = -INFINITY; }
            }

            float mx0 = s0[0], mx1 = s1[0];
            #pragma unroll
            for (int j = 1; j < 7; ++j) { mx0 = fmaxf(mx0, s0[j]); mx1 = fmaxf(mx1, s1[j]); }
            #pragma unroll
            for (int o = 16; o > 0; o >>= 1) {
                mx0 = fmaxf(mx0, __shfl_xor_sync(0xffffffffu, mx0, o));
                mx1 = fmaxf(mx1, __shfl_xor_sync(0xffffffffu, mx1, o));
            }
            float p0[7], p1[7], sum0 = 0.f, sum1 = 0.f;
            #pragma unroll
            for (int j = 0; j < 7; ++j) {
                p0[j] = __expf(s0[j] - mx0); sum0 += p0[j];
                p1[j] = __expf(s1[j] - mx1); sum1 += p1[j];
            }
            #pragma unroll
            for (int o = 16; o > 0; o >>= 1) {
                sum0 += __shfl_xor_sync(0xffffffffu, sum0, o);
                sum1 += __shfl_xor_sync(0xffffffffu, sum1, o);
            }
            #pragma unroll
            for (int j = 0; j < 7; ++j) {
                int y = j*32 + lane;
                if (y < Fn) {
                    attnT[y*AP + rt0] = p0[j];
                    if (v1) attnT[y*AP + rt1] = p1[j];
                }
            }
            if (lane == 0) {
                rscale[rt0] = 1.f / sum0;
                if (v1) rscale[rt1] = 1.f / sum1;
            }
        }
        __syncthreads();    // attnT + rscale visible

        // ---- GEMM: each group accumulates its y half (2-deep pipeline) ----
        ull acc[32];
        #pragma unroll
        for (int i = 0; i < 32; ++i) acc[i] = 0ull;

        if (gemm_on) {
            const float* aB = attnT + (size_t)y0*AP + tr*8;
            const float* hB = hs + (size_t)y0*E2n + tc*8;

            float4 avA0 = *(const float4*)&aB[0*AP];
            float4 avA1 = *(const float4*)&aB[0*AP + 4];
            double2 hA0 = *(const double2*)&hB[0*E2n];
            double2 hA1 = *(const double2*)&hB[0*E2n + 4];
            float4 avB0 = *(const float4*)&aB[1*AP];
            float4 avB1 = *(const float4*)&aB[1*AP + 4];
            double2 hB0 = *(const double2*)&hB[1*E2n];
            double2 hB1 = *(const double2*)&hB[1*E2n + 4];

            #pragma unroll 1
            for (int y = 0; y < KSPLIT - 2; y += 2) {
                GEMM_STEP(avA0, avA1, hA0, hA1);
                avA0 = *(const float4*)&aB[(y+2)*AP];
                avA1 = *(const float4*)&aB[(y+2)*AP + 4];
                hA0  = *(const double2*)&hB[(y+2)*E2n];
                hA1  = *(const double2*)&hB[(y+2)*E2n + 4];
                GEMM_STEP(avB0, avB1, hB0, hB1);
                avB0 = *(const float4*)&aB[(y+3)*AP];
                avB1 = *(const float4*)&aB[(y+3)*AP + 4];
                hB0  = *(const double2*)&hB[(y+3)*E2n];
                hB1  = *(const double2*)&hB[(y+3)*E2n + 4];
            }
            GEMM_STEP(avA0, avA1, hA0, hA1);
            GEMM_STEP(avB0, avB1, hB0, hB1);
        }
        __syncthreads();    // both groups done reading attnT

        // ---- reduction: group B parks partials in attnT region ----
        float* red = attnT;
        if (grp == 1 && gemm_on) {
            #pragma unroll
            for (int r = 0; r < 8; ++r) {
                float2 v0 = unpk(acc[r*4+0]);
                float2 v1 = unpk(acc[r*4+1]);
                float2 v2 = unpk(acc[r*4+2]);
                float2 v3 = unpk(acc[r*4+3]);
                float* rp = &red[(size_t)(tr*8 + r)*AP + tc*8];
                *(float4*)rp       = make_float4(v0.x, v0.y, v1.x, v1.y);
                *(float4*)(rp + 4) = make_float4(v2.x, v2.y, v3.x, v3.y);
            }
        }
        __syncthreads();    // partials visible

        // ---- group A: add partials, scale, store ----
        if (grp == 0 && gemm_on) {
            #pragma unroll
            for (int r = 0; r < 8; ++r) {
                int rt = tr*8 + r;
                if (rt < valid) {
                    const float* rp = &red[(size_t)rt*AP + tc*8];
                    double2 b0 = *(const double2*)rp;
                    double2 b1 = *(const double2*)(rp + 4);
                    add2(acc[r*4+0], d2l(b0.x));
                    add2(acc[r*4+1], d2l(b0.y));
                    add2(acc[r*4+2], d2l(b1.x));
                    add2(acc[r*4+3], d2l(b1.y));

                    int f = t0 + rt;
                    float sc = rscale[rt];
                    float2 v0 = unpk(acc[r*4+0]);
                    float2 v1 = unpk(acc[r*4+1]);
                    float2 v2 = unpk(acc[r*4+2]);
                    float2 v3 = unpk(acc[r*4+3]);
                    size_t o = ((size_t)b*Fn + f) * (Hn*E2n) + (size_t)h*E2n + tc*8;
                    *(float4*)&out[o]     = make_float4(v0.x*sc, v0.y*sc, v1.x*sc, v1.y*sc);
                    *(float4*)&out[o + 4] = make_float4(v2.x*sc, v2.y*sc, v3.x*sc, v3.y*sc);
                }
            }
        }
        __syncthreads();   // attnT/rscale reuse by next tile
    }
}

// ---------------------------------------------------------------------------

extern "C" void kernel_launch(void* const* d_in, const int* in_sizes, int n_in,
                              void* d_out, int out_size) {
    const float* x   = (const float*)d_in[0];
    const float* adj = (const float*)d_in[1];
    const float* W   = (const float*)d_in[2];
    const float* a   = (const float*)d_in[3];
    float* out = (float*)d_out;

    const int SMEM_A = (128*65 + 64*128) * 4;                      // 66,048 B
    const int SMEM_B = (Fn*E2n + Fn*AP + Fn + Fn + TROWS) * 4;     // 210,112 B
    cudaFuncSetAttribute(k_proj, cudaFuncAttributeMaxDynamicSharedMemorySize, SMEM_A);
    cudaFuncSetAttribute(k_attn, cudaFuncAttributeMaxDynamicSharedMemorySize, SMEM_B);

    k_proj<<<ROWS/128, 256, SMEM_A>>>(x, W, a);             // 400 CTAs
    k_attn<<<dim3(Hn, Bn), 512, SMEM_B>>>(adj, out);        // 1,024 CTAs
}